// round 1
// baseline (speedup 1.0000x reference)
#include <cuda_runtime.h>
#include <math.h>

// Problem constants (from reference)
#define B_ 4096
#define T_ 256
#define V_ 16
#define E_ 10
#define H_ 50
#define O_ 16

// Only x[b, T-1] matters (h_t[:, -1]); output depends solely on the token
// value in [0,16). Each block computes the 16x16 token->output table in
// shared memory, then gathers per row.
__global__ __launch_bounds__(128, 1)
void dclstm_kernel(const int* __restrict__ x,
                   const float* __restrict__ emb,
                   const float* __restrict__ w1,
                   const float* __restrict__ b1,
                   const float* __restrict__ b2,
                   const float* __restrict__ w_out,
                   const float* __restrict__ b_out,
                   float* __restrict__ out)
{
    __shared__ float table[V_ * O_];   // 16 tokens x 16 outputs

    const int tid = threadIdx.x;

    if (tid < V_) {
        const int v = tid;
        // Embedding row
        float xe[E_];
#pragma unroll
        for (int e = 0; e < E_; ++e) xe[e] = emb[v * E_ + e];

        // LSTM-cell-like pipeline, only channels used by the reference:
        //   i: [0,50), o: [100,150), g: [150,200)
        float h[H_];
#pragma unroll
        for (int j = 0; j < H_; ++j) {
            float pi = b1[j]        + b2[j];
            float po = b1[100 + j]  + b2[100 + j];
            float pg = b1[150 + j]  + b2[150 + j];
#pragma unroll
            for (int e = 0; e < E_; ++e) {
                const float xev = xe[e];
                pi = fmaf(w1[(j)        * E_ + e], xev, pi);
                po = fmaf(w1[(100 + j)  * E_ + e], xev, po);
                pg = fmaf(w1[(150 + j)  * E_ + e], xev, pg);
            }
            const float it = 1.0f / (1.0f + expf(-pi));
            const float ot = 1.0f / (1.0f + expf(-po));
            const float g  = tanhf(pg);
            const float ct = it * g;
            h[j] = ot * tanhf(ct);
        }

        // Output projection: table[v][k] = h . w_out[k] + b_out[k]
#pragma unroll
        for (int k = 0; k < O_; ++k) {
            float s = b_out[k];
#pragma unroll
            for (int j = 0; j < H_; ++j)
                s = fmaf(h[j], w_out[k * H_ + j], s);
            table[v * O_ + k] = s;
        }
    }
    __syncthreads();

    // One row per thread: 32 blocks * 128 threads = 4096 rows
    const int row = blockIdx.x * blockDim.x + tid;
    if (row < B_) {
        const int tok = x[row * T_ + (T_ - 1)];
        const float4* src = reinterpret_cast<const float4*>(&table[tok * O_]);
        float4* dst = reinterpret_cast<float4*>(out + row * O_);
        dst[0] = src[0];
        dst[1] = src[1];
        dst[2] = src[2];
        dst[3] = src[3];
    }
}

extern "C" void kernel_launch(void* const* d_in, const int* in_sizes, int n_in,
                              void* d_out, int out_size)
{
    // metadata order: x, emb, w1, b1, w2, b2, w_out, b_out
    const int*   x     = (const int*)  d_in[0];
    const float* emb   = (const float*)d_in[1];
    const float* w1    = (const float*)d_in[2];
    const float* b1    = (const float*)d_in[3];
    // d_in[4] = w2 (unused by the reference)
    const float* b2    = (const float*)d_in[5];
    const float* w_out = (const float*)d_in[6];
    const float* b_out = (const float*)d_in[7];
    float* out = (float*)d_out;

    dclstm_kernel<<<B_ / 128, 128>>>(x, emb, w1, b1, b2, w_out, b_out, out);
}

// round 2
// speedup vs baseline: 3.7232x; 3.7232x over previous
#include <cuda_runtime.h>
#include <math.h>

#define B_ 4096
#define T_ 256
#define V_ 16
#define E_ 10
#define H_ 50
#define O_ 16

// sigmoid / tanh via MUFU (EX2 + RCP): ~1e-6 rel error, well under the 1e-3 budget.
__device__ __forceinline__ float fast_sigmoid(float x) {
    return __fdividef(1.0f, 1.0f + __expf(-x));
}
__device__ __forceinline__ float fast_tanh(float x) {
    // tanh(x) = 2*sigmoid(2x) - 1
    return fmaf(2.0f, __fdividef(1.0f, 1.0f + __expf(-2.0f * x)), -1.0f);
}

// Only x[b, T-1] matters; output depends solely on the token value in [0,16).
// Each block (redundantly) builds the 16x16 token->output table with ALL 128
// threads cooperating, then gathers one row per thread.
__global__ __launch_bounds__(128, 1)
void dclstm_kernel(const int* __restrict__ x,
                   const float* __restrict__ emb,
                   const float* __restrict__ w1,
                   const float* __restrict__ b1,
                   const float* __restrict__ b2,
                   const float* __restrict__ w_out,
                   const float* __restrict__ b_out,
                   float* __restrict__ out)
{
    __shared__ float sh_h[V_][H_];       // 16 x 50 hidden states
    __shared__ float table[V_ * O_];     // 16 x 16 outputs

    const int tid = threadIdx.x;
    const int row = blockIdx.x * 128 + tid;

    // Prefetch this row's token NOW; DRAM latency hides under table compute.
    const int tok = x[row * T_ + (T_ - 1)];

    // ---- Phase 1: hidden states. 128 threads = 16 tokens x 8 lanes. ----
    {
        const int v    = tid >> 3;        // token 0..15
        const int lane = tid & 7;         // 0..7

        float xe[E_];
#pragma unroll
        for (int e = 0; e < E_; ++e) xe[e] = emb[v * E_ + e];

        // hidden units j = lane, lane+8, ... (<=7 per thread)
        for (int j = lane; j < H_; j += 8) {
            float pi = b1[j]       + b2[j];
            float po = b1[100 + j] + b2[100 + j];
            float pg = b1[150 + j] + b2[150 + j];
#pragma unroll
            for (int e = 0; e < E_; ++e) {
                const float xev = xe[e];
                pi = fmaf(w1[(j)       * E_ + e], xev, pi);
                po = fmaf(w1[(100 + j) * E_ + e], xev, po);
                pg = fmaf(w1[(150 + j) * E_ + e], xev, pg);
            }
            const float it = fast_sigmoid(pi);
            const float ot = fast_sigmoid(po);
            const float g  = fast_tanh(pg);
            sh_h[v][j] = ot * fast_tanh(it * g);
        }
    }
    __syncthreads();

    // ---- Phase 2: output projection. 256 table entries, 2 per thread. ----
#pragma unroll
    for (int r = 0; r < 2; ++r) {
        const int idx = tid + r * 128;    // 0..255
        const int v = idx >> 4;
        const int k = idx & 15;
        float s = b_out[k];
#pragma unroll
        for (int j = 0; j < H_; ++j)
            s = fmaf(sh_h[v][j], w_out[k * H_ + j], s);
        table[idx] = s;
    }
    __syncthreads();

    // ---- Phase 3: gather (token already in register). ----
    const float4* src = reinterpret_cast<const float4*>(&table[tok * O_]);
    float4* dst = reinterpret_cast<float4*>(out + row * O_);
    dst[0] = src[0];
    dst[1] = src[1];
    dst[2] = src[2];
    dst[3] = src[3];
}

extern "C" void kernel_launch(void* const* d_in, const int* in_sizes, int n_in,
                              void* d_out, int out_size)
{
    // metadata order: x, emb, w1, b1, w2, b2, w_out, b_out
    const int*   x     = (const int*)  d_in[0];
    const float* emb   = (const float*)d_in[1];
    const float* w1    = (const float*)d_in[2];
    const float* b1    = (const float*)d_in[3];
    // d_in[4] = w2 (unused by the reference)
    const float* b2    = (const float*)d_in[5];
    const float* w_out = (const float*)d_in[6];
    const float* b_out = (const float*)d_in[7];
    float* out = (float*)d_out;

    dclstm_kernel<<<B_ / 128, 128>>>(x, emb, w1, b1, b2, w_out, b_out, out);
}